// round 14
// baseline (speedup 1.0000x reference)
#include <cuda_runtime.h>
#include <cstdint>

// Scratch: j-reduced weights, squashed rows, and per-batch ready flags.
__device__ float g_wsum[256 * 256];   // Wsum[m][k] = sum_j W[j][m][k]
__device__ float g_o[512 * 256];      // o[b][k]
__device__ int   g_flag[512];         // o[b] ready flag (cleared by wsum)

// ---------------------------------------------------------------------------
// Kernel A: Wsum[m,k] = sum_j W[j,m,k].   W: [256][256][256] fp32.
// 512 blocks x 256 thr; warp reads 512B contiguous; 8 j-groups x 32 j.
// Blocks 0/1 also clear the per-batch flags for this replay (visible to the
// fused kernel via the kernel boundary).
// ---------------------------------------------------------------------------
__global__ void __launch_bounds__(256) wsum_kernel(const float* __restrict__ W) {
    if (blockIdx.x < 2) {
        g_flag[blockIdx.x * 256 + threadIdx.x] = 0;
    }

    const int lane = threadIdx.x & 31;
    const int jg   = threadIdx.x >> 5;
    const int col  = blockIdx.x * 32 + lane;

    const float4* __restrict__ W4 = (const float4*)W;
    float4 acc = make_float4(0.f, 0.f, 0.f, 0.f);
    const int j0 = jg * 32;
#pragma unroll 16
    for (int j = 0; j < 32; ++j) {
        float4 w = __ldg(&W4[(size_t)(j0 + j) * 16384 + col]);
        acc.x += w.x; acc.y += w.y; acc.z += w.z; acc.w += w.w;
    }

    __shared__ float4 sh[256];
    sh[threadIdx.x] = acc;
    __syncthreads();

    if (jg == 0) {
        float4 r = sh[lane];
#pragma unroll
        for (int g = 1; g < 8; ++g) {
            float4 p = sh[g * 32 + lane];
            r.x += p.x; r.y += p.y; r.z += p.z; r.w += p.w;
        }
        ((float4*)g_wsum)[col] = r;
    }
}

// ---------------------------------------------------------------------------
// Kernel BC (fused): grid 4224 x 256.
//   blocks 0..127   : compute o[b] for 4 batch rows each, publish per-b flags
//                     (cumulative release at gpu scope).
//   blocks 128..4223: acquire-spin on their batch's flag, then stream 32
//                     i-rows. Intra-kernel shared data (g_o) is read with
//                     __ldcg (L2-coherent) — never __ldg/.nc, whose per-SM RO
//                     cache is not coherent with mid-kernel writes (R10 bug).
// Wave-1 dispatch takes the lowest bids: all 128 producers are resident from
// the start (8 CTAs/SM -> wave 1 ~ 1184 blocks); spinners nanosleep-back off
// and retire as flags land. No circular dependency -> no deadlock.
// ---------------------------------------------------------------------------
__global__ void __launch_bounds__(256) fused_bc_kernel(const float* __restrict__ inputs,
                                                       float* __restrict__ out) {
    const int bid = blockIdx.x;
    const int t   = threadIdx.x;

    if (bid < 128) {
        // ---- compute o for b0..b0+3 ----
        const int b0 = bid * 4;

        __shared__ float in_sh[4][256];
        __shared__ float red[4][8];

#pragma unroll
        for (int bb = 0; bb < 4; ++bb)
            in_sh[bb][t] = inputs[(b0 + bb) * 256 + t];
        __syncthreads();

        float a0 = 0.f, a1 = 0.f, a2 = 0.f, a3 = 0.f;
#pragma unroll 8
        for (int m = 0; m < 256; ++m) {
            const float w = g_wsum[m * 256 + t];
            a0 = fmaf(in_sh[0][m], w, a0);
            a1 = fmaf(in_sh[1][m], w, a1);
            a2 = fmaf(in_sh[2][m], w, a2);
            a3 = fmaf(in_sh[3][m], w, a3);
        }

        float v[4] = { a0 * (1.f/256.f), a1 * (1.f/256.f),
                       a2 * (1.f/256.f), a3 * (1.f/256.f) };

#pragma unroll
        for (int bb = 0; bb < 4; ++bb) {
            float sq = v[bb] * v[bb];
#pragma unroll
            for (int o = 16; o > 0; o >>= 1)
                sq += __shfl_xor_sync(0xffffffffu, sq, o);
            if ((t & 31) == 0) red[bb][t >> 5] = sq;
        }
        __syncthreads();

#pragma unroll
        for (int bb = 0; bb < 4; ++bb) {
            const float* r = red[bb];
            const float s2 = ((r[0] + r[1]) + (r[2] + r[3])) +
                             ((r[4] + r[5]) + (r[6] + r[7]));
            const float scale = s2 / (1.0f + s2) / sqrtf(s2 + 1e-7f);
            g_o[(b0 + bb) * 256 + t] = scale * v[bb];
        }
        __syncthreads();   // all g_o writes of this block done

        if (t < 4) {
            // Cumulative release: barrier above + release store publishes the
            // whole block's g_o writes at gpu scope (L2 = point of coherence).
            int* f = &g_flag[b0 + t];
            asm volatile("st.global.release.gpu.b32 [%0], %1;"
                         :: "l"(f), "r"(1) : "memory");
        }
    } else {
        // ---- broadcast 32 i-rows for batch b once o[b] is ready ----
        const int idx   = bid - 128;
        const int b     = idx >> 3;
        const int chunk = idx & 7;
        const int col   = t & 63;
        const int r0    = t >> 6;

        if (t == 0) {
            const int* f = &g_flag[b];
            int v;
            do {
                asm volatile("ld.global.acquire.gpu.b32 %0, [%1];"
                             : "=r"(v) : "l"(f) : "memory");
                if (v) break;
                __nanosleep(32);
            } while (true);
        }
        __syncthreads();   // block ordered after thread 0's acquire

        // L2-coherent read (bypasses the non-coherent per-SM RO/L1 path).
        const float4 o4 = __ldcg(&((const float4*)g_o)[b * 64 + col]);
        float4* __restrict__ dst = (float4*)out + (size_t)b * 16384
                                   + (size_t)(chunk * 32) * 64 + col;
#pragma unroll
        for (int s = 0; s < 8; ++s)
            dst[(size_t)(r0 + 4 * s) * 64] = o4;
    }
}

extern "C" void kernel_launch(void* const* d_in, const int* in_sizes, int n_in,
                              void* d_out, int out_size) {
    const float* inputs = (const float*)d_in[0];  // [512, 256]
    const float* W      = (const float*)d_in[1];  // [256, 256, 256]
    if (n_in >= 2 && in_sizes[0] > in_sizes[1]) {
        const float* tmp = inputs; inputs = W; W = tmp;
    }
    float* out = (float*)d_out;  // [512, 256, 256]

    wsum_kernel<<<512, 256>>>(W);
    fused_bc_kernel<<<4224, 256>>>(inputs, out);
    (void)out_size;
}

// round 15
// speedup vs baseline: 1.1759x; 1.1759x over previous
#include <cuda_runtime.h>
#include <cstdint>

// Scratch: j-reduced weights and squashed per-batch output row.
__device__ float g_wsum[256 * 256];   // Wsum[m][k] = sum_j W[j][m][k]
__device__ float g_o[512 * 256];      // o[b][k]

// ---------------------------------------------------------------------------
// Kernel A: Wsum[m,k] = sum_j W[j,m,k].   W: [256][256][256] fp32.
// 512 blocks x 256 thr; warp reads 32 f4 = 512B contiguous per load.
// 8 j-groups x 32 j per thread, unroll 16 -> deep load pipeline.
// (Best-measured wsum shape: 13.82-13.86 us.)
// ---------------------------------------------------------------------------
__global__ void __launch_bounds__(256) wsum_kernel(const float* __restrict__ W) {
    const int lane = threadIdx.x & 31;          // f4-col within stripe
    const int jg   = threadIdx.x >> 5;          // j-group 0..7
    const int col  = blockIdx.x * 32 + lane;    // global f4 column 0..16383

    const float4* __restrict__ W4 = (const float4*)W;
    float4 acc = make_float4(0.f, 0.f, 0.f, 0.f);
    const int j0 = jg * 32;
#pragma unroll 16
    for (int j = 0; j < 32; ++j) {
        float4 w = __ldg(&W4[(size_t)(j0 + j) * 16384 + col]);
        acc.x += w.x; acc.y += w.y; acc.z += w.z; acc.w += w.w;
    }

    __shared__ float4 sh[256];
    sh[threadIdx.x] = acc;
    __syncthreads();

    if (jg == 0) {
        float4 r = sh[lane];
#pragma unroll
        for (int g = 1; g < 8; ++g) {
            float4 p = sh[g * 32 + lane];
            r.x += p.x; r.y += p.y; r.z += p.z; r.w += p.w;
        }
        ((float4*)g_wsum)[col] = r;
    }
}

// ---------------------------------------------------------------------------
// Kernel B: o[b,k]. 128 blocks x 512 threads; 4 batch rows per block.
// m split across 2 thread-groups -> 128-load chains; smem combine.
// (Measured ~3 us.)
// ---------------------------------------------------------------------------
__global__ void __launch_bounds__(512) compute_o_kernel(const float* __restrict__ inputs) {
    const int b0 = blockIdx.x * 4;
    const int t  = threadIdx.x;        // 0..511
    const int k  = t & 255;
    const int mh = t >> 8;             // 0 or 1
    const int m0 = mh * 128;

    __shared__ float in_sh[4][256];
    __shared__ float part[4][256];
    __shared__ float red[4][8];

    if (t < 256) {
#pragma unroll
        for (int bb = 0; bb < 4; ++bb)
            in_sh[bb][t] = inputs[(b0 + bb) * 256 + t];
    }
    __syncthreads();

    float a0 = 0.f, a1 = 0.f, a2 = 0.f, a3 = 0.f;
#pragma unroll 8
    for (int mm = 0; mm < 128; ++mm) {
        const int m = m0 + mm;
        const float w = g_wsum[m * 256 + k];
        a0 = fmaf(in_sh[0][m], w, a0);
        a1 = fmaf(in_sh[1][m], w, a1);
        a2 = fmaf(in_sh[2][m], w, a2);
        a3 = fmaf(in_sh[3][m], w, a3);
    }
    if (mh == 1) {
        part[0][k] = a0; part[1][k] = a1; part[2][k] = a2; part[3][k] = a3;
    }
    __syncthreads();

    if (mh == 0) {
        float v[4];
        v[0] = (a0 + part[0][k]) * (1.f/256.f);
        v[1] = (a1 + part[1][k]) * (1.f/256.f);
        v[2] = (a2 + part[2][k]) * (1.f/256.f);
        v[3] = (a3 + part[3][k]) * (1.f/256.f);

#pragma unroll
        for (int bb = 0; bb < 4; ++bb) {
            float sq = v[bb] * v[bb];
#pragma unroll
            for (int o = 16; o > 0; o >>= 1)
                sq += __shfl_xor_sync(0xffffffffu, sq, o);
            if ((k & 31) == 0) red[bb][k >> 5] = sq;
        }
        __syncthreads();

#pragma unroll
        for (int bb = 0; bb < 4; ++bb) {
            const float* r = red[bb];
            const float s2 = ((r[0] + r[1]) + (r[2] + r[3])) +
                             ((r[4] + r[5]) + (r[6] + r[7]));
            const float scale = s2 / (1.0f + s2) / sqrtf(s2 + 1e-7f);
            g_o[(b0 + bb) * 256 + k] = scale * v[bb];
        }
    } else {
        __syncthreads();  // match barrier count
    }
}

// ---------------------------------------------------------------------------
// Kernel C: out[b,i,k] = o[b,k].  134 MB store stream, streaming STG.128.
// 4096 blocks = 512 b x 8 chunks of 32 i-rows; 8 stores per thread.
// (The 48.7 us configuration's store path.)
// ---------------------------------------------------------------------------
__global__ void __launch_bounds__(256) broadcast_kernel(float* __restrict__ out) {
    const int b     = blockIdx.x >> 3;
    const int chunk = blockIdx.x & 7;
    const int t     = threadIdx.x;
    const int col   = t & 63;
    const int r0    = t >> 6;

    const float4 o4 = __ldg(&((const float4*)g_o)[b * 64 + col]);
    float4* __restrict__ dst = (float4*)out + (size_t)b * 16384
                               + (size_t)(chunk * 32) * 64 + col;
#pragma unroll
    for (int s = 0; s < 8; ++s)
        __stcs(dst + (size_t)(r0 + 4 * s) * 64, o4);
}

extern "C" void kernel_launch(void* const* d_in, const int* in_sizes, int n_in,
                              void* d_out, int out_size) {
    const float* inputs = (const float*)d_in[0];  // [512, 256]
    const float* W      = (const float*)d_in[1];  // [256, 256, 256]
    if (n_in >= 2 && in_sizes[0] > in_sizes[1]) {
        const float* tmp = inputs; inputs = W; W = tmp;
    }
    float* out = (float*)d_out;  // [512, 256, 256]

    wsum_kernel<<<512, 256>>>(W);
    compute_o_kernel<<<128, 512>>>(inputs);
    broadcast_kernel<<<4096, 256>>>(out);
    (void)out_size;
}